// round 2
// baseline (speedup 1.0000x reference)
#include <cuda_runtime.h>
#include <cstdint>

#define KNS 16
#define KNV 8
#define KHE 32
#define KD  40
#define KWN 640
#define KNODES 10000
#define KEDGES 160000
#define KC110 0.5773502691896258f
#define KC111 0.7071067811865476f
#define KEPS  1e-5f

// shared memory layout (bytes)
#define SM_P1 163840                 // after P2 (640*32 float2)
#define SM_B2 172032
#define SM_B1 177152
#define SM_BYTES 177408

// ---------------------------------------------------------------------------
// device scratch (static -- no cudaMalloc allowed)
// ---------------------------------------------------------------------------
__device__ float    g_qnode[KNODES * KD];
__device__ float    g_attn[KEDGES];
__device__ float    g_vedge[KEDGES * KD];
__device__ unsigned g_maxkey[KNODES];
__device__ float    g_denom[KNODES];
__device__ float    g_upd[KNODES * KD];
__device__ float    g_stats[40];

// ---------------------------------------------------------------------------
// packed f32x2 helpers (FFMA2 only reachable via PTX)
// ---------------------------------------------------------------------------
__device__ __forceinline__ unsigned long long ffma2(unsigned long long a,
                                                    unsigned long long b,
                                                    unsigned long long c) {
  unsigned long long d;
  asm("fma.rn.f32x2 %0, %1, %2, %3;" : "=l"(d) : "l"(a), "l"(b), "l"(c));
  return d;
}
__device__ __forceinline__ unsigned long long fadd2(unsigned long long a,
                                                    unsigned long long b) {
  unsigned long long d;
  asm("add.rn.f32x2 %0, %1, %2;" : "=l"(d) : "l"(a), "l"(b));
  return d;
}
__device__ __forceinline__ unsigned long long pk2(float lo, float hi) {
  unsigned long long r;
  asm("mov.b64 %0, {%1, %2};" : "=l"(r) : "f"(lo), "f"(hi));
  return r;
}
__device__ __forceinline__ void upk2(unsigned long long v, float& lo, float& hi) {
  asm("mov.b64 {%0, %1}, %2;" : "=f"(lo), "=f"(hi) : "l"(v));
}

// orderable-uint encoding for float atomicMax
__device__ __forceinline__ unsigned fenc(float f) {
  unsigned u = __float_as_uint(f);
  return (u & 0x80000000u) ? ~u : (u | 0x80000000u);
}
__device__ __forceinline__ float fdec(unsigned k) {
  return (k & 0x80000000u) ? __uint_as_float(k & 0x7FFFFFFFu)
                           : __uint_as_float(~k);
}

// one packed weight column (32 x float2) . packed hidden vector
__device__ __forceinline__ float2 dotcol(const ulonglong2* __restrict__ col,
                                         unsigned long long bias,
                                         const unsigned long long h2[KHE]) {
  unsigned long long a0 = bias, a1 = 0ull, a2 = 0ull, a3 = 0ull;
#pragma unroll
  for (int t = 0; t < 8; t++) {
    ulonglong2 wA = col[2 * t];
    ulonglong2 wB = col[2 * t + 1];
    a0 = ffma2(h2[4 * t + 0], wA.x, a0);
    a1 = ffma2(h2[4 * t + 1], wA.y, a1);
    a2 = ffma2(h2[4 * t + 2], wB.x, a2);
    a3 = ffma2(h2[4 * t + 3], wB.y, a3);
  }
  a0 = fadd2(fadd2(a0, a1), fadd2(a2, a3));
  float lo, hi;
  upk2(a0, lo, hi);
  return make_float2(lo, hi);
}

// ---------------------------------------------------------------------------
__global__ void zero_kernel() {
  int i = blockIdx.x * blockDim.x + threadIdx.x;
  if (i < KNODES * KD) g_upd[i] = 0.f;
  if (i < KNODES) {
    g_maxkey[i] = 0u;
    g_denom[i] = 0.f;
  }
  if (i < 40) g_stats[i] = 0.f;
}

// per-node query projection
__global__ void qnode_kernel(const float* __restrict__ atom,
                             const float* __restrict__ Wqs,
                             const float* __restrict__ Wqv) {
  int n = blockIdx.x * blockDim.x + threadIdx.x;
  if (n >= KNODES) return;
  const float* a = atom + (size_t)n * KD;
  float s[KNS], v[KNV * 3];
#pragma unroll
  for (int i = 0; i < KNS; i++) s[i] = a[i];
#pragma unroll
  for (int i = 0; i < KNV * 3; i++) v[i] = a[KNS + i];
  float* q = g_qnode + (size_t)n * KD;
#pragma unroll
  for (int o = 0; o < KNS; o++) {
    float acc = 0.f;
#pragma unroll
    for (int i = 0; i < KNS; i++) acc = fmaf(s[i], __ldg(&Wqs[i * KNS + o]), acc);
    q[o] = acc;
  }
#pragma unroll
  for (int o = 0; o < KNV; o++) {
    float a0 = 0.f, a1 = 0.f, a2 = 0.f;
#pragma unroll
    for (int i = 0; i < KNV; i++) {
      float w = __ldg(&Wqv[i * KNV + o]);
      a0 = fmaf(v[3 * i + 0], w, a0);
      a1 = fmaf(v[3 * i + 1], w, a1);
      a2 = fmaf(v[3 * i + 2], w, a2);
    }
    q[KNS + 3 * o + 0] = a0;
    q[KNS + 3 * o + 1] = a1;
    q[KNS + 3 * o + 2] = a2;
  }
}

// ---------------------------------------------------------------------------
// fused per-edge kernel: dual MLP (k,v packed in f32x2) + tensor-product
// epilogue -> attn logit + v-edge(40), and segment max over src
// ---------------------------------------------------------------------------
__global__ void __launch_bounds__(256, 1) edge_kernel(
    const float* __restrict__ atom, const float* __restrict__ ef,
    const float* __restrict__ shp, const int* __restrict__ eidx,
    const float* __restrict__ kw1, const float* __restrict__ kb1,
    const float* __restrict__ kw2, const float* __restrict__ kb2,
    const float* __restrict__ vw1, const float* __restrict__ vb1,
    const float* __restrict__ vw2, const float* __restrict__ vb2) {
  extern __shared__ unsigned char smem[];
  float2* sP2f = (float2*)(smem);
  float2* sP1f = (float2*)(smem + SM_P1);
  float2* sB2f = (float2*)(smem + SM_B2);
  float2* sB1f = (float2*)(smem + SM_B1);

  int tid = threadIdx.x;
  for (int idx = tid; idx < KWN * KHE; idx += blockDim.x) {
    int p = idx >> 5, j = idx & 31;
    sP2f[idx] = make_float2(kw2[j * KWN + p], vw2[j * KWN + p]);
  }
  for (int idx = tid; idx < KHE * KHE; idx += blockDim.x)
    sP1f[idx] = make_float2(kw1[idx], vw1[idx]);
  for (int idx = tid; idx < KWN; idx += blockDim.x)
    sB2f[idx] = make_float2(kb2[idx], vb2[idx]);
  for (int idx = tid; idx < KHE; idx += blockDim.x)
    sB1f[idx] = make_float2(kb1[idx], vb1[idx]);
  __syncthreads();

  const ulonglong2* sP2 = (const ulonglong2*)sP2f;
  const ulonglong2* sP1 = (const ulonglong2*)sP1f;
  const unsigned long long* sB2u = (const unsigned long long*)sB2f;
  const unsigned long long* sB1u = (const unsigned long long*)sB1f;

  const int gstride = gridDim.x * blockDim.x;
  for (int e = blockIdx.x * blockDim.x + tid; e < KEDGES; e += gstride) {
    const int dst = eidx[e];
    const int src = eidx[KEDGES + e];

    float4 sh4 = *(const float4*)(shp + 4 * (size_t)e);
    const float shs = sh4.x, s0 = sh4.y, s1 = sh4.z, s2 = sh4.w;

    // atom[dst] -> xs, xv
    const float4* ar = (const float4*)(atom + (size_t)dst * KD);
    float xs[KNS], xv[KNV * 3];
#pragma unroll
    for (int t = 0; t < 4; t++) {
      float4 w = ar[t];
      xs[4 * t + 0] = w.x; xs[4 * t + 1] = w.y;
      xs[4 * t + 2] = w.z; xs[4 * t + 3] = w.w;
    }
#pragma unroll
    for (int t = 0; t < 6; t++) {
      float4 w = ar[4 + t];
      xv[4 * t + 0] = w.x; xv[4 * t + 1] = w.y;
      xv[4 * t + 2] = w.z; xv[4 * t + 3] = w.w;
    }

    // q[src] -> qs, qv (register-resident, static indexing only)
    const float4* qr = (const float4*)(g_qnode + (size_t)src * KD);
    float qs[KNS], qv[KNV * 3];
#pragma unroll
    for (int t = 0; t < 4; t++) {
      float4 w = qr[t];
      qs[4 * t + 0] = w.x; qs[4 * t + 1] = w.y;
      qs[4 * t + 2] = w.z; qs[4 * t + 3] = w.w;
    }
#pragma unroll
    for (int t = 0; t < 6; t++) {
      float4 w = qr[4 + t];
      qv[4 * t + 0] = w.x; qv[4 * t + 1] = w.y;
      qv[4 * t + 2] = w.z; qv[4 * t + 3] = w.w;
    }

    // per-edge TP coefficients (dynamic-indexed in main loop -> local mem, cheap)
    float cA[24];
    float tB[96];
#pragma unroll
    for (int i = 0; i < 16; i++) cA[i] = xs[i] * shs;
#pragma unroll
    for (int i = 0; i < 8; i++) {
      float d = xv[3 * i] * s0 + xv[3 * i + 1] * s1 + xv[3 * i + 2] * s2;
      cA[16 + i] = KC110 * d;
    }
#pragma unroll
    for (int i = 0; i < 16; i++) {
      tB[3 * i + 0] = xs[i] * s0;
      tB[3 * i + 1] = xs[i] * s1;
      tB[3 * i + 2] = xs[i] * s2;
    }
#pragma unroll
    for (int i = 0; i < 8; i++) {
      tB[48 + 3 * i + 0] = shs * xv[3 * i + 0];
      tB[48 + 3 * i + 1] = shs * xv[3 * i + 1];
      tB[48 + 3 * i + 2] = shs * xv[3 * i + 2];
    }
#pragma unroll
    for (int i = 0; i < 8; i++) {
      float a0 = xv[3 * i], a1 = xv[3 * i + 1], a2 = xv[3 * i + 2];
      tB[72 + 3 * i + 0] = KC111 * (a1 * s2 - a2 * s1);
      tB[72 + 3 * i + 1] = KC111 * (a2 * s0 - a0 * s2);
      tB[72 + 3 * i + 2] = KC111 * (a0 * s1 - a1 * s0);
    }

    // hidden layer, both MLPs packed
    unsigned long long h2[KHE];
#pragma unroll
    for (int o = 0; o < KHE; o++) h2[o] = sB1u[o];
    const float* efr = ef + (size_t)e * KHE;
    for (int j = 0; j < KHE; j++) {
      float fj = __ldg(efr + j);
      unsigned long long fj2 = pk2(fj, fj);
      const ulonglong2* row = sP1 + j * 16;
#pragma unroll
      for (int t = 0; t < 16; t++) {
        ulonglong2 w = row[t];
        h2[2 * t + 0] = ffma2(fj2, w.x, h2[2 * t + 0]);
        h2[2 * t + 1] = ffma2(fj2, w.y, h2[2 * t + 1]);
      }
    }
#pragma unroll
    for (int o = 0; o < KHE; o++) {
      float a, b;
      upk2(h2[o], a, b);
      h2[o] = pk2(fmaxf(a, 0.f), fmaxf(b, 0.f));
    }

    // stream 640 packed (wk,wv) columns into the TP epilogue
    float attn = 0.f;
    float outs[KNS], outv[KNV * 3];
#pragma unroll
    for (int o = 0; o < KNS; o++) outs[o] = 0.f;
#pragma unroll
    for (int o = 0; o < KNV * 3; o++) outv[o] = 0.f;

    const ulonglong2* col = sP2;
    const unsigned long long* bias = sB2u;
    for (int ii = 0; ii < 24; ii++) {            // w1 (16x16) + w2 (8x16)
      float ci = cA[ii];
#pragma unroll
      for (int o = 0; o < 16; o++) {
        float2 w = dotcol(col, bias[o], h2);
        attn = fmaf(w.x * ci, qs[o], attn);
        outs[o] = fmaf(w.y, ci, outs[o]);
        col += 16;
      }
      bias += 16;
    }
    for (int jj = 0; jj < 32; jj++) {            // w3 (16x8) + w4 (8x8) + w5 (8x8)
      float t0 = tB[3 * jj], t1 = tB[3 * jj + 1], t2 = tB[3 * jj + 2];
#pragma unroll
      for (int o = 0; o < 8; o++) {
        float2 w = dotcol(col, bias[o], h2);
        float tq = t0 * qv[3 * o] + t1 * qv[3 * o + 1] + t2 * qv[3 * o + 2];
        attn = fmaf(w.x, tq, attn);
        outv[3 * o + 0] = fmaf(w.y, t0, outv[3 * o + 0]);
        outv[3 * o + 1] = fmaf(w.y, t1, outv[3 * o + 1]);
        outv[3 * o + 2] = fmaf(w.y, t2, outv[3 * o + 2]);
        col += 16;
      }
      bias += 8;
    }

    g_attn[e] = attn;
    atomicMax(&g_maxkey[src], fenc(attn));
    float4* vr = (float4*)(g_vedge + (size_t)e * KD);
#pragma unroll
    for (int t = 0; t < 4; t++)
      vr[t] = make_float4(outs[4 * t], outs[4 * t + 1], outs[4 * t + 2], outs[4 * t + 3]);
#pragma unroll
    for (int t = 0; t < 6; t++)
      vr[4 + t] = make_float4(outv[4 * t], outv[4 * t + 1], outv[4 * t + 2], outv[4 * t + 3]);
  }
}

// e = exp(attn - m[src]); accumulate denom and unnormalized e*v
__global__ void scatter_kernel(const int* __restrict__ eidx) {
  int e = blockIdx.x * blockDim.x + threadIdx.x;
  if (e >= KEDGES) return;
  int src = eidx[KEDGES + e];
  float m = fdec(g_maxkey[src]);
  float ex = expf(g_attn[e] - m);
  atomicAdd(&g_denom[src], ex);
  const float* v = g_vedge + (size_t)e * KD;
  float* u = g_upd + (size_t)src * KD;
#pragma unroll
  for (int d = 0; d < KD; d++) atomicAdd(u + d, ex * __ldg(v + d));
}

// x = atom + upd/denom; accumulate batchnorm stats
__global__ void nodeA_kernel(const float* __restrict__ atom) {
  __shared__ float st[40];
  int tid = threadIdx.x;
  if (tid < 40) st[tid] = 0.f;
  __syncthreads();
  int n = blockIdx.x * blockDim.x + tid;
  if (n < KNODES) {
    float den = g_denom[n];
    float inv = den > 0.f ? 1.f / den : 0.f;
    float x[KD];
#pragma unroll
    for (int d = 0; d < KD; d++) {
      float xv_ = atom[(size_t)n * KD + d] + g_upd[(size_t)n * KD + d] * inv;
      x[d] = xv_;
      g_upd[(size_t)n * KD + d] = xv_;
    }
#pragma unroll
    for (int c = 0; c < 16; c++) {
      atomicAdd(&st[c], x[c]);
      atomicAdd(&st[16 + c], x[c] * x[c]);
    }
#pragma unroll
    for (int c = 0; c < 8; c++) {
      float v0 = x[16 + 3 * c], v1 = x[16 + 3 * c + 1], v2 = x[16 + 3 * c + 2];
      atomicAdd(&st[32 + c], v0 * v0 + v1 * v1 + v2 * v2);
    }
  }
  __syncthreads();
  if (tid < 40) atomicAdd(&g_stats[tid], st[tid]);
}

// batchnorm apply -> d_out node section
__global__ void nodeB_kernel(const float* __restrict__ bnws,
                             const float* __restrict__ bnbs,
                             const float* __restrict__ bnwv,
                             float* __restrict__ out) {
  int n = blockIdx.x * blockDim.x + threadIdx.x;
  if (n >= KNODES) return;
  const float invN = 1.f / (float)KNODES;
  const float* x = g_upd + (size_t)n * KD;
  float* o = out + (size_t)n * KD;
#pragma unroll
  for (int c = 0; c < 16; c++) {
    float mu = g_stats[c] * invN;
    float var = g_stats[16 + c] * invN - mu * mu;
    o[c] = (x[c] - mu) * rsqrtf(var + KEPS) * __ldg(&bnws[c]) + __ldg(&bnbs[c]);
  }
#pragma unroll
  for (int c = 0; c < 8; c++) {
    float norm = g_stats[32 + c] * (invN / 3.f);
    float sc = rsqrtf(norm + KEPS) * __ldg(&bnwv[c]);
    o[16 + 3 * c + 0] = x[16 + 3 * c + 0] * sc;
    o[16 + 3 * c + 1] = x[16 + 3 * c + 1] * sc;
    o[16 + 3 * c + 2] = x[16 + 3 * c + 2] * sc;
  }
}

// copy edge_features into the second output slot
__global__ void copy_kernel(const float* __restrict__ ef, float* __restrict__ out) {
  int i = blockIdx.x * blockDim.x + threadIdx.x;
  const float4* s = (const float4*)ef;
  float4* d = (float4*)out;
  int n4 = (KEDGES * KHE) / 4;
  if (i < n4) d[i] = s[i];
}

extern "C" void kernel_launch(void* const* d_in, const int* in_sizes, int n_in,
                              void* d_out, int out_size) {
  const float* atom = (const float*)d_in[0];
  const float* ef   = (const float*)d_in[1];
  const float* shp  = (const float*)d_in[2];
  const float* Wqs  = (const float*)d_in[3];
  const float* Wqv  = (const float*)d_in[4];
  const float* kw1  = (const float*)d_in[5];
  const float* kb1  = (const float*)d_in[6];
  const float* kw2  = (const float*)d_in[7];
  const float* kb2  = (const float*)d_in[8];
  const float* vw1  = (const float*)d_in[9];
  const float* vb1  = (const float*)d_in[10];
  const float* vw2  = (const float*)d_in[11];
  const float* vb2  = (const float*)d_in[12];
  const float* bnws = (const float*)d_in[13];
  const float* bnbs = (const float*)d_in[14];
  const float* bnwv = (const float*)d_in[15];
  const int*   eidx = (const int*)d_in[16];
  float* out = (float*)d_out;

  cudaFuncSetAttribute(edge_kernel, cudaFuncAttributeMaxDynamicSharedMemorySize,
                       SM_BYTES);

  zero_kernel<<<(KNODES * KD + 255) / 256, 256>>>();
  qnode_kernel<<<(KNODES + 255) / 256, 256>>>(atom, Wqs, Wqv);
  edge_kernel<<<148, 256, SM_BYTES>>>(atom, ef, shp, eidx, kw1, kb1, kw2, kb2,
                                      vw1, vb1, vw2, vb2);
  scatter_kernel<<<(KEDGES + 255) / 256, 256>>>(eidx);
  nodeA_kernel<<<(KNODES + 255) / 256, 256>>>(atom);
  nodeB_kernel<<<(KNODES + 255) / 256, 256>>>(bnws, bnbs, bnwv,
                                              out);
  copy_kernel<<<(KEDGES * KHE / 4 + 255) / 256, 256>>>(ef, out + KNODES * KD);
}

// round 6
// speedup vs baseline: 1.2182x; 1.2182x over previous
#include <cuda_runtime.h>
#include <cstdint>

#define KNS 16
#define KNV 8
#define KHE 32
#define KD  40
#define KWN 640
#define KNODES 10000
#define KEDGES 160000
#define KC110 0.5773502691896258f
#define KC111 0.7071067811865476f
#define KEPS  1e-5f

// shared memory layout (bytes)
#define SM_P1 163840                 // after P2 (640*32 float2)
#define SM_B2 172032
#define SM_B1 177152
#define SM_BYTES 177408

// ---------------------------------------------------------------------------
// device scratch (static -- no cudaMalloc allowed)
// ---------------------------------------------------------------------------
__device__ float    g_qnode[KNODES * KD];
__device__ float    g_attn[KEDGES];
__device__ float    g_eval[KEDGES];
__device__ float    g_vedge[KEDGES * KD];
__device__ unsigned g_maxkey[KNODES];
__device__ float    g_denom[KNODES];
__device__ float    g_upd[KNODES * KD];
__device__ float    g_stats[40];
// per-edge TP coefficients, TRANSPOSED [coef][edge] for coalesced access:
// rows 0..23 = cA, rows 24..119 = tB
__device__ float    g_coef[120 * KEDGES];

// ---------------------------------------------------------------------------
// packed f32x2 helpers (FFMA2 only reachable via PTX)
// ---------------------------------------------------------------------------
__device__ __forceinline__ unsigned long long ffma2(unsigned long long a,
                                                    unsigned long long b,
                                                    unsigned long long c) {
  unsigned long long d;
  asm("fma.rn.f32x2 %0, %1, %2, %3;" : "=l"(d) : "l"(a), "l"(b), "l"(c));
  return d;
}
__device__ __forceinline__ unsigned long long fadd2(unsigned long long a,
                                                    unsigned long long b) {
  unsigned long long d;
  asm("add.rn.f32x2 %0, %1, %2;" : "=l"(d) : "l"(a), "l"(b));
  return d;
}
__device__ __forceinline__ unsigned long long pk2(float lo, float hi) {
  unsigned long long r;
  asm("mov.b64 %0, {%1, %2};" : "=l"(r) : "f"(lo), "f"(hi));
  return r;
}
__device__ __forceinline__ void upk2(unsigned long long v, float& lo, float& hi) {
  asm("mov.b64 {%0, %1}, %2;" : "=f"(lo), "=f"(hi) : "l"(v));
}

// orderable-uint encoding for float atomicMax
__device__ __forceinline__ unsigned fenc(float f) {
  unsigned u = __float_as_uint(f);
  return (u & 0x80000000u) ? ~u : (u | 0x80000000u);
}
__device__ __forceinline__ float fdec(unsigned k) {
  return (k & 0x80000000u) ? __uint_as_float(k & 0x7FFFFFFFu)
                           : __uint_as_float(~k);
}

// One packed weight column (32 x float2) . packed hidden vector -> packed (k,v).
// MACRO, not a function: h2 must never be address-taken so it stays in regs.
#define DOTCOL(RES, COLP, BIASV)                                              \
  do {                                                                        \
    unsigned long long _a0 = (BIASV), _a1 = 0ull, _a2 = 0ull, _a3 = 0ull;     \
    _Pragma("unroll")                                                         \
    for (int _t = 0; _t < 8; _t++) {                                          \
      ulonglong2 _wA = (COLP)[2 * _t];                                        \
      ulonglong2 _wB = (COLP)[2 * _t + 1];                                    \
      _a0 = ffma2(h2[4 * _t + 0], _wA.x, _a0);                                \
      _a1 = ffma2(h2[4 * _t + 1], _wA.y, _a1);                                \
      _a2 = ffma2(h2[4 * _t + 2], _wB.x, _a2);                                \
      _a3 = ffma2(h2[4 * _t + 3], _wB.y, _a3);                                \
    }                                                                         \
    (RES) = fadd2(fadd2(_a0, _a1), fadd2(_a2, _a3));                          \
  } while (0)

// ---------------------------------------------------------------------------
__global__ void zero_kernel() {
  int i = blockIdx.x * blockDim.x + threadIdx.x;
  if (i < KNODES * KD) g_upd[i] = 0.f;
  if (i < KNODES) {
    g_maxkey[i] = 0u;
    g_denom[i] = 0.f;
  }
  if (i < 40) g_stats[i] = 0.f;
}

// per-node query projection
__global__ void qnode_kernel(const float* __restrict__ atom,
                             const float* __restrict__ Wqs,
                             const float* __restrict__ Wqv) {
  int n = blockIdx.x * blockDim.x + threadIdx.x;
  if (n >= KNODES) return;
  const float* a = atom + (size_t)n * KD;
  float s[KNS], v[KNV * 3];
#pragma unroll
  for (int i = 0; i < KNS; i++) s[i] = a[i];
#pragma unroll
  for (int i = 0; i < KNV * 3; i++) v[i] = a[KNS + i];
  float* q = g_qnode + (size_t)n * KD;
#pragma unroll
  for (int o = 0; o < KNS; o++) {
    float acc = 0.f;
#pragma unroll
    for (int i = 0; i < KNS; i++) acc = fmaf(s[i], __ldg(&Wqs[i * KNS + o]), acc);
    q[o] = acc;
  }
#pragma unroll
  for (int o = 0; o < KNV; o++) {
    float a0 = 0.f, a1 = 0.f, a2 = 0.f;
#pragma unroll
    for (int i = 0; i < KNV; i++) {
      float w = __ldg(&Wqv[i * KNV + o]);
      a0 = fmaf(v[3 * i + 0], w, a0);
      a1 = fmaf(v[3 * i + 1], w, a1);
      a2 = fmaf(v[3 * i + 2], w, a2);
    }
    q[KNS + 3 * o + 0] = a0;
    q[KNS + 3 * o + 1] = a1;
    q[KNS + 3 * o + 2] = a2;
  }
}

// ---------------------------------------------------------------------------
// per-edge TP coefficients -> g_coef (transposed).  All static indexing: the
// scalar values live in named registers, every STG row index is a literal.
// ---------------------------------------------------------------------------
__global__ void coef_kernel(const float* __restrict__ atom,
                            const float* __restrict__ shp,
                            const int* __restrict__ eidx) {
  int e = blockIdx.x * blockDim.x + threadIdx.x;
  if (e >= KEDGES) return;
  const int dst = eidx[e];

  float4 sh4 = *(const float4*)(shp + 4 * (size_t)e);
  const float shs = sh4.x, s0 = sh4.y, s1 = sh4.z, s2 = sh4.w;

  const float4* ar = (const float4*)(atom + (size_t)dst * KD);
  float xs[KNS], xv[KNV * 3];
#pragma unroll
  for (int t = 0; t < 4; t++) {
    float4 w = ar[t];
    xs[4 * t + 0] = w.x; xs[4 * t + 1] = w.y;
    xs[4 * t + 2] = w.z; xs[4 * t + 3] = w.w;
  }
#pragma unroll
  for (int t = 0; t < 6; t++) {
    float4 w = ar[4 + t];
    xv[4 * t + 0] = w.x; xv[4 * t + 1] = w.y;
    xv[4 * t + 2] = w.z; xv[4 * t + 3] = w.w;
  }

  float* c = g_coef + e;     // column e; row stride KEDGES (coalesced per warp)
  // rows 0..15: cA for w1 block
#pragma unroll
  for (int i = 0; i < 16; i++) c[(size_t)i * KEDGES] = xs[i] * shs;
  // rows 16..23: cA for w2 block
#pragma unroll
  for (int i = 0; i < 8; i++) {
    float d = xv[3 * i] * s0 + xv[3 * i + 1] * s1 + xv[3 * i + 2] * s2;
    c[(size_t)(16 + i) * KEDGES] = KC110 * d;
  }
  // rows 24..71: tB for w3 block (x_s * sh_v)
#pragma unroll
  for (int i = 0; i < 16; i++) {
    c[(size_t)(24 + 3 * i + 0) * KEDGES] = xs[i] * s0;
    c[(size_t)(24 + 3 * i + 1) * KEDGES] = xs[i] * s1;
    c[(size_t)(24 + 3 * i + 2) * KEDGES] = xs[i] * s2;
  }
  // rows 72..95: tB for w4 block (sh_s * x_v)
#pragma unroll
  for (int i = 0; i < 8; i++) {
    c[(size_t)(72 + 3 * i + 0) * KEDGES] = shs * xv[3 * i + 0];
    c[(size_t)(72 + 3 * i + 1) * KEDGES] = shs * xv[3 * i + 1];
    c[(size_t)(72 + 3 * i + 2) * KEDGES] = shs * xv[3 * i + 2];
  }
  // rows 96..119: tB for w5 block (C111 * cross(x_v, sh_v))
#pragma unroll
  for (int i = 0; i < 8; i++) {
    float a0 = xv[3 * i], a1 = xv[3 * i + 1], a2 = xv[3 * i + 2];
    c[(size_t)(96 + 3 * i + 0) * KEDGES] = KC111 * (a1 * s2 - a2 * s1);
    c[(size_t)(96 + 3 * i + 1) * KEDGES] = KC111 * (a2 * s0 - a0 * s2);
    c[(size_t)(96 + 3 * i + 2) * KEDGES] = KC111 * (a0 * s1 - a1 * s0);
  }
}

// ---------------------------------------------------------------------------
// fused per-edge kernel: dual MLP + fully-packed TP epilogue.
// No local arrays: coefficients stream in via coalesced LDG from g_coef.
// ---------------------------------------------------------------------------
__global__ void __launch_bounds__(256, 1) edge_kernel(
    const float* __restrict__ ef, const int* __restrict__ eidx,
    const float* __restrict__ kw1, const float* __restrict__ kb1,
    const float* __restrict__ kw2, const float* __restrict__ kb2,
    const float* __restrict__ vw1, const float* __restrict__ vb1,
    const float* __restrict__ vw2, const float* __restrict__ vb2) {
  extern __shared__ unsigned char smem[];
  float2* sP2f = (float2*)(smem);
  float2* sP1f = (float2*)(smem + SM_P1);
  float2* sB2f = (float2*)(smem + SM_B2);
  float2* sB1f = (float2*)(smem + SM_B1);

  int tid = threadIdx.x;
  for (int idx = tid; idx < KWN * KHE; idx += blockDim.x) {
    int p = idx >> 5, j = idx & 31;
    sP2f[idx] = make_float2(kw2[j * KWN + p], vw2[j * KWN + p]);
  }
  for (int idx = tid; idx < KHE * KHE; idx += blockDim.x)
    sP1f[idx] = make_float2(kw1[idx], vw1[idx]);
  for (int idx = tid; idx < KWN; idx += blockDim.x)
    sB2f[idx] = make_float2(kb2[idx], vb2[idx]);
  for (int idx = tid; idx < KHE; idx += blockDim.x)
    sB1f[idx] = make_float2(kb1[idx], vb1[idx]);
  __syncthreads();

  const ulonglong2* sP2 = (const ulonglong2*)sP2f;
  const ulonglong2* sP1 = (const ulonglong2*)sP1f;
  const unsigned long long* sB2u = (const unsigned long long*)sB2f;
  const unsigned long long* sB1u = (const unsigned long long*)sB1f;

  const int gstride = gridDim.x * blockDim.x;
  for (int e = blockIdx.x * blockDim.x + tid; e < KEDGES; e += gstride) {
    const int src = eidx[KEDGES + e];

    // hidden layer, both MLPs packed; outer loop dynamic (small code),
    // inner fully unrolled so h2 indexing stays static -> registers.
    unsigned long long h2[KHE];
#pragma unroll
    for (int o = 0; o < KHE; o++) h2[o] = sB1u[o];
    {
      const float4* efr4 = (const float4*)(ef + (size_t)e * KHE);
      const ulonglong2* row = sP1;
#pragma unroll 1
      for (int t4 = 0; t4 < 8; t4++) {
        float4 w4 = efr4[t4];
#pragma unroll
        for (int u = 0; u < 4; u++) {
          float fj = (u == 0) ? w4.x : (u == 1) ? w4.y : (u == 2) ? w4.z : w4.w;
          unsigned long long fj2 = pk2(fj, fj);
#pragma unroll
          for (int t = 0; t < 16; t++) {
            ulonglong2 w = row[t];
            h2[2 * t + 0] = ffma2(fj2, w.x, h2[2 * t + 0]);
            h2[2 * t + 1] = ffma2(fj2, w.y, h2[2 * t + 1]);
          }
          row += 16;
        }
      }
    }
#pragma unroll
    for (int o = 0; o < KHE; o++) {
      float a, b;
      upk2(h2[o], a, b);
      h2[o] = pk2(fmaxf(a, 0.f), fmaxf(b, 0.f));
    }

    // packed epilogue: stream 640 (wk,wv) columns; coefficient per outer
    // iteration arrives as ONE coalesced LDG (no local arrays anywhere).
    unsigned long long outs2[KNS];
    unsigned long long outv2[KNV * 3];
#pragma unroll
    for (int o = 0; o < KNS; o++) outs2[o] = 0ull;
#pragma unroll
    for (int o = 0; o < KNV * 3; o++) outv2[o] = 0ull;

    const float* coef = g_coef + e;
    const ulonglong2* col = sP2;
    const unsigned long long* bias = sB2u;
#pragma unroll 1
    for (int ii = 0; ii < 24; ii++) {            // w1 (16x16) + w2 (8x16)
      float cif = __ldg(coef + (size_t)ii * KEDGES);
      unsigned long long ci2 = pk2(cif, cif);
#pragma unroll
      for (int o = 0; o < 16; o++) {
        unsigned long long w2;
        DOTCOL(w2, col, bias[o]);
        outs2[o] = ffma2(w2, ci2, outs2[o]);
        col += 16;
      }
      bias += 16;
    }
#pragma unroll 1
    for (int jj = 0; jj < 32; jj++) {            // w3 (16x8) + w4 (8x8) + w5 (8x8)
      float f0 = __ldg(coef + (size_t)(24 + 3 * jj + 0) * KEDGES);
      float f1 = __ldg(coef + (size_t)(24 + 3 * jj + 1) * KEDGES);
      float f2 = __ldg(coef + (size_t)(24 + 3 * jj + 2) * KEDGES);
      unsigned long long t0 = pk2(f0, f0), t1 = pk2(f1, f1), t2 = pk2(f2, f2);
#pragma unroll
      for (int o = 0; o < 8; o++) {
        unsigned long long w2;
        DOTCOL(w2, col, bias[o]);
        outv2[3 * o + 0] = ffma2(w2, t0, outv2[3 * o + 0]);
        outv2[3 * o + 1] = ffma2(w2, t1, outv2[3 * o + 1]);
        outv2[3 * o + 2] = ffma2(w2, t2, outv2[3 * o + 2]);
        col += 16;
      }
      bias += 8;
    }

    // finale: unpack, dot k-lane with q[src], store v-lane
    const float4* qr = (const float4*)(g_qnode + (size_t)src * KD);
    float attn = 0.f;
    float4* vr = (float4*)(g_vedge + (size_t)e * KD);
#pragma unroll
    for (int t = 0; t < 4; t++) {
      float4 qw = qr[t];
      float k0, k1, k2, k3, w0, w1, w2, w3;
      upk2(outs2[4 * t + 0], k0, w0);
      upk2(outs2[4 * t + 1], k1, w1);
      upk2(outs2[4 * t + 2], k2, w2);
      upk2(outs2[4 * t + 3], k3, w3);
      attn = fmaf(k0, qw.x, attn);
      attn = fmaf(k1, qw.y, attn);
      attn = fmaf(k2, qw.z, attn);
      attn = fmaf(k3, qw.w, attn);
      vr[t] = make_float4(w0, w1, w2, w3);
    }
#pragma unroll
    for (int t = 0; t < 6; t++) {
      float4 qw = qr[4 + t];
      float k0, k1, k2, k3, w0, w1, w2, w3;
      upk2(outv2[4 * t + 0], k0, w0);
      upk2(outv2[4 * t + 1], k1, w1);
      upk2(outv2[4 * t + 2], k2, w2);
      upk2(outv2[4 * t + 3], k3, w3);
      attn = fmaf(k0, qw.x, attn);
      attn = fmaf(k1, qw.y, attn);
      attn = fmaf(k2, qw.z, attn);
      attn = fmaf(k3, qw.w, attn);
      vr[4 + t] = make_float4(w0, w1, w2, w3);
    }

    g_attn[e] = attn;
    atomicMax(&g_maxkey[src], fenc(attn));
  }
}

// per-edge exp + denom accumulation
__global__ void eval_kernel(const int* __restrict__ eidx) {
  int e = blockIdx.x * blockDim.x + threadIdx.x;
  if (e >= KEDGES) return;
  int src = eidx[KEDGES + e];
  float m = fdec(g_maxkey[src]);
  float ex = expf(g_attn[e] - m);
  g_eval[e] = ex;
  atomicAdd(&g_denom[src], ex);
}

// coalesced scatter: one thread per (edge, dim)
__global__ void scatter_kernel(const int* __restrict__ eidx) {
  int i = blockIdx.x * blockDim.x + threadIdx.x;
  if (i >= KEDGES * KD) return;
  int e = i / KD;
  int d = i - e * KD;
  int src = __ldg(&eidx[KEDGES + e]);
  float ex = __ldg(&g_eval[e]);
  atomicAdd(&g_upd[(size_t)src * KD + d], ex * g_vedge[i]);
}

// x = atom + upd/denom; accumulate batchnorm stats via warp shfl reduction
__global__ void nodeA_kernel(const float* __restrict__ atom) {
  int tid = threadIdx.x;
  int n = blockIdx.x * blockDim.x + tid;
  float x[KD];
  if (n < KNODES) {
    float den = g_denom[n];
    float inv = den > 0.f ? 1.f / den : 0.f;
#pragma unroll
    for (int d = 0; d < KD; d++) {
      float xv_ = atom[(size_t)n * KD + d] + g_upd[(size_t)n * KD + d] * inv;
      x[d] = xv_;
      g_upd[(size_t)n * KD + d] = xv_;
    }
  } else {
#pragma unroll
    for (int d = 0; d < KD; d++) x[d] = 0.f;
  }
  float st[40];
#pragma unroll
  for (int c = 0; c < 16; c++) {
    st[c] = x[c];
    st[16 + c] = x[c] * x[c];
  }
#pragma unroll
  for (int c = 0; c < 8; c++) {
    float v0 = x[16 + 3 * c], v1 = x[16 + 3 * c + 1], v2 = x[16 + 3 * c + 2];
    st[32 + c] = v0 * v0 + v1 * v1 + v2 * v2;
  }
#pragma unroll
  for (int c = 0; c < 40; c++) {
#pragma unroll
    for (int off = 16; off > 0; off >>= 1)
      st[c] += __shfl_down_sync(0xFFFFFFFFu, st[c], off);
  }
  if ((tid & 31) == 0) {
#pragma unroll
    for (int c = 0; c < 40; c++) atomicAdd(&g_stats[c], st[c]);
  }
}

// batchnorm apply -> d_out node section
__global__ void nodeB_kernel(const float* __restrict__ bnws,
                             const float* __restrict__ bnbs,
                             const float* __restrict__ bnwv,
                             float* __restrict__ out) {
  int n = blockIdx.x * blockDim.x + threadIdx.x;
  if (n >= KNODES) return;
  const float invN = 1.f / (float)KNODES;
  const float* x = g_upd + (size_t)n * KD;
  float* o = out + (size_t)n * KD;
#pragma unroll
  for (int c = 0; c < 16; c++) {
    float mu = g_stats[c] * invN;
    float var = g_stats[16 + c] * invN - mu * mu;
    o[c] = (x[c] - mu) * rsqrtf(var + KEPS) * __ldg(&bnws[c]) + __ldg(&bnbs[c]);
  }
#pragma unroll
  for (int c = 0; c < 8; c++) {
    float norm = g_stats[32 + c] * (invN / 3.f);
    float sc = rsqrtf(norm + KEPS) * __ldg(&bnwv[c]);
    o[16 + 3 * c + 0] = x[16 + 3 * c + 0] * sc;
    o[16 + 3 * c + 1] = x[16 + 3 * c + 1] * sc;
    o[16 + 3 * c + 2] = x[16 + 3 * c + 2] * sc;
  }
}

// copy edge_features into the second output slot
__global__ void copy_kernel(const float* __restrict__ ef, float* __restrict__ out) {
  int i = blockIdx.x * blockDim.x + threadIdx.x;
  const float4* s = (const float4*)ef;
  float4* d = (float4*)out;
  int n4 = (KEDGES * KHE) / 4;
  if (i < n4) d[i] = s[i];
}

extern "C" void kernel_launch(void* const* d_in, const int* in_sizes, int n_in,
                              void* d_out, int out_size) {
  const float* atom = (const float*)d_in[0];
  const float* ef   = (const float*)d_in[1];
  const float* shp  = (const float*)d_in[2];
  const float* Wqs  = (const float*)d_in[3];
  const float* Wqv  = (const float*)d_in[4];
  const float* kw1  = (const float*)d_in[5];
  const float* kb1  = (const float*)d_in[6];
  const float* kw2  = (const float*)d_in[7];
  const float* kb2  = (const float*)d_in[8];
  const float* vw1  = (const float*)d_in[9];
  const float* vb1  = (const float*)d_in[10];
  const float* vw2  = (const float*)d_in[11];
  const float* vb2  = (const float*)d_in[12];
  const float* bnws = (const float*)d_in[13];
  const float* bnbs = (const float*)d_in[14];
  const float* bnwv = (const float*)d_in[15];
  const int*   eidx = (const int*)d_in[16];
  float* out = (float*)d_out;

  cudaFuncSetAttribute(edge_kernel, cudaFuncAttributeMaxDynamicSharedMemorySize,
                       SM_BYTES);

  zero_kernel<<<(KNODES * KD + 255) / 256, 256>>>();
  qnode_kernel<<<(KNODES + 255) / 256, 256>>>(atom, Wqs, Wqv);
  coef_kernel<<<(KEDGES + 255) / 256, 256>>>(atom, shp, eidx);  // launch #3
  edge_kernel<<<148, 256, SM_BYTES>>>(ef, eidx, kw1, kb1, kw2, kb2,
                                      vw1, vb1, vw2, vb2);      // launch #4 (ncu)
  eval_kernel<<<(KEDGES + 255) / 256, 256>>>(eidx);
  scatter_kernel<<<(KEDGES * KD + 319) / 320, 320>>>(eidx);
  nodeA_kernel<<<(KNODES + 255) / 256, 256>>>(atom);
  nodeB_kernel<<<(KNODES + 255) / 256, 256>>>(bnws, bnbs, bnwv, out);
  copy_kernel<<<(KEDGES * KHE / 4 + 255) / 256, 256>>>(ef, out + KNODES * KD);
}